// round 15
// baseline (speedup 1.0000x reference)
#include <cuda_runtime.h>
#include <math.h>

#define NB 128
#define NP 625
#define NENC 512
#define NA 256
#define NE 256
#define NH 512
#define NV 70
#define NT 70
#define NG 2048
#define KC 64
#define START_TOK 68
#define END_TOK 69
#define CHK 157  // p-chunk length (last chunk = 154)

// ---------------- scratch ----------------
__device__ float g_att1[NB * NP * NA];   // 81.92MB
__device__ float g_h[NB * NH];
__device__ float g_c[NB * NH];
__device__ float g_mean[NB * NENC];
__device__ float g_x[NB * NH];           // gated awe
__device__ float g_a2p[4][NB * NA];      // att2 K-partials
__device__ float g_gtp[4][NB * NENC];    // gate  K-partials
__device__ float g_xp[4][NB * NENC];     // awe chunk-partials
__device__ float g_gw[2][NB * NG];       // h@Whh K-partials
__device__ float g_wp[2][NB * NG];       // awe@Wih2 K-partials
__device__ float g_embW[NV * NG];        // emb @ Wih[0:256] per vocab token
__device__ float g_lstmb[NG];            // bih + bhh
__device__ float g_WfcT[NV * NH];
__device__ float g_stat[NB * 8];         // per-b, per-chunk (M, S)
__device__ float g_rowval[NB];
__device__ int   g_rowflat[NB];
__device__ int   g_tok[NB];
__device__ int   g_cnt[NB];              // softmax-stats epoch counter (4/step/b)
__device__ int   g_cnt2[NB];             // awe-partials epoch counter (4/step/b)
__device__ int   g_cnt3;                 // h-ready epoch counter (128/step)
__device__ int   g_done[1];

// ---------------- f32x2 helpers ----------------
__device__ __forceinline__ unsigned long long fma2(unsigned long long a, unsigned long long b,
                                                   unsigned long long c) {
    unsigned long long d;
    asm("fma.rn.f32x2 %0, %1, %2, %3;" : "=l"(d) : "l"(a), "l"(b), "l"(c));
    return d;
}
__device__ __forceinline__ float2 unpack2(unsigned long long v) {
    float2 r;
    asm("mov.b64 {%0, %1}, %2;" : "=f"(r.x), "=f"(r.y) : "l"(v));
    return r;
}
__device__ __forceinline__ float sigmoidf_(float x) { return 1.f / (1.f + expf(-x)); }

// ---------------- core GEMM tile: C[128, c0:c0+32] = A[128,K] @ W[K, ldw] ----------------
__device__ __forceinline__ void gemm128x32(const float* __restrict__ A, int lda,
                                           const float* __restrict__ W, int ldw, int c0, int K,
                                           unsigned long long acc[8], float* As, float2* Bs) {
    const int tid = threadIdx.x;
    const int ai = (tid >> 4) * 2;
    const int bi = tid & 15;
    const int la_m = tid & 127, la_k = (tid >> 7) * 32;
    const int lb_n = tid & 31, lb_k = tid >> 5;
#pragma unroll
    for (int j = 0; j < 8; j++) acc[j] = 0ULL;
    float4 pa[8];
    float pb[8];
    const float* Arow = A + (size_t)la_m * lda + la_k;
    const float* Wcol = W + (size_t)lb_k * ldw + c0 + lb_n;
#pragma unroll
    for (int j = 0; j < 8; j++) pa[j] = *(const float4*)(Arow + 4 * j);
#pragma unroll
    for (int j = 0; j < 8; j++) pb[j] = Wcol[(size_t)(8 * j) * ldw];
    const int nc = K / KC;
    for (int ch = 0;;) {
#pragma unroll
        for (int j = 0; j < 8; j++) {
            float4 v = pa[j];
            int kk = la_k + 4 * j;
            As[(kk + 0) * 128 + la_m] = v.x;
            As[(kk + 1) * 128 + la_m] = v.y;
            As[(kk + 2) * 128 + la_m] = v.z;
            As[(kk + 3) * 128 + la_m] = v.w;
        }
#pragma unroll
        for (int j = 0; j < 8; j++) Bs[(lb_k + 8 * j) * 32 + lb_n] = make_float2(pb[j], pb[j]);
        __syncthreads();
        if (ch + 1 < nc) {
            const float* Ar2 = Arow + (ch + 1) * KC;
            const float* Wc2 = Wcol + (size_t)((ch + 1) * KC) * ldw;
#pragma unroll
            for (int j = 0; j < 8; j++) pa[j] = *(const float4*)(Ar2 + 4 * j);
#pragma unroll
            for (int j = 0; j < 8; j++) pb[j] = Wc2[(size_t)(8 * j) * ldw];
        }
        const ulonglong2* As2 = (const ulonglong2*)As;
        const ulonglong2* Bs2 = (const ulonglong2*)Bs;
#pragma unroll 8
        for (int k = 0; k < KC; k++) {
            ulonglong2 bv = Bs2[k * 16 + bi];
            ulonglong2 a01 = As2[k * 32 + ai];
            ulonglong2 a23 = As2[k * 32 + ai + 1];
            acc[0] = fma2(a01.x, bv.x, acc[0]);
            acc[1] = fma2(a01.x, bv.y, acc[1]);
            acc[2] = fma2(a01.y, bv.x, acc[2]);
            acc[3] = fma2(a01.y, bv.y, acc[3]);
            acc[4] = fma2(a23.x, bv.x, acc[4]);
            acc[5] = fma2(a23.x, bv.y, acc[5]);
            acc[6] = fma2(a23.y, bv.x, acc[6]);
            acc[7] = fma2(a23.y, bv.y, acc[7]);
        }
        __syncthreads();
        if (++ch == nc) break;
    }
}

__device__ __forceinline__ void store_tile_raw(float* out, int ldo, int c0,
                                               const unsigned long long acc[8]) {
    int tid = threadIdx.x;
    int m8 = (tid >> 4) * 8, n2 = (tid & 15) * 2;
#pragma unroll
    for (int mp = 0; mp < 4; mp++)
#pragma unroll
        for (int nn = 0; nn < 2; nn++) {
            float2 v = unpack2(acc[mp * 2 + nn]);
            int r = m8 + 2 * mp, c = c0 + n2 + nn;
            out[(size_t)r * ldo + c] = v.x;
            out[(size_t)(r + 1) * ldo + c] = v.y;
        }
}

// ---------------- init ----------------
__global__ void k_init(const float* __restrict__ enc, const float* __restrict__ Wfc,
                       const float* __restrict__ bih, const float* __restrict__ bhh,
                       const float* __restrict__ emb, const float* __restrict__ Wih) {
    __shared__ float es[NE];
    int bx = blockIdx.x, tid = threadIdx.x;  // 512 threads
    if (bx < NB) {
        const float* eb = enc + (size_t)bx * NP * NENC + tid;
        float s0 = 0.f, s1 = 0.f, s2 = 0.f, s3 = 0.f, s4 = 0.f;
#pragma unroll 5
        for (int p = 0; p < NP; p += 5) {
            s0 += eb[(size_t)(p + 0) * NENC];
            s1 += eb[(size_t)(p + 1) * NENC];
            s2 += eb[(size_t)(p + 2) * NENC];
            s3 += eb[(size_t)(p + 3) * NENC];
            s4 += eb[(size_t)(p + 4) * NENC];
        }
        g_mean[bx * NENC + tid] = (((s0 + s1) + (s2 + s3)) + s4) / 625.0f;
        if (tid == 0) {
            g_rowval[bx] = -INFINITY;
            g_rowflat[bx] = 0;
            g_tok[bx] = START_TOK;
            g_cnt[bx] = 0;
            g_cnt2[bx] = 0;
        }
        if (bx == 0 && tid == 0) {
            g_done[0] = 0;
            g_cnt3 = 0;
        }
    } else if (bx < NB + NV) {
        int col = bx - NB;
        g_WfcT[col * NH + tid] = Wfc[tid * NV + col];
    } else if (bx < NB + NV + 4) {
        int j = (bx - NB - NV) * 512 + tid;
        g_lstmb[j] = bih[j] + bhh[j];
    } else {
        int idx = bx - (NB + NV + 4);
        int t = idx >> 2, seg = idx & 3;
        if (tid < NE) es[tid] = emb[t * NE + tid];
        __syncthreads();
        int col = seg * 512 + tid;
        float acc = 0.f;
#pragma unroll 8
        for (int k = 0; k < NE; k++) acc = fmaf(es[k], Wih[(size_t)k * NG + col], acc);
        g_embW[t * NG + col] = acc;
    }
}

// ---------------- att1 = enc @ We + be  +  h0/c0 (merged) ----------------
__global__ __launch_bounds__(256) void k_att1(const float* __restrict__ enc,
                                              const float* __restrict__ We,
                                              const float* __restrict__ be,
                                              const float* __restrict__ Wh0,
                                              const float* __restrict__ bh0,
                                              const float* __restrict__ Wc0,
                                              const float* __restrict__ bc0) {
    __shared__ __align__(16) float As[KC * 128];
    __shared__ __align__(16) float2 Bs[KC * 32];
    int bx = blockIdx.x, tid = threadIdx.x;
    unsigned long long acc[8];
    int m8 = (tid >> 4) * 8, n2 = (tid & 15) * 2;
    if (bx < 5000) {
        int mt = bx >> 3, c0 = (bx & 7) * 32;
        gemm128x32(enc + (size_t)mt * 128 * NENC, NENC, We, NA, c0, NENC, acc, As, Bs);
        float* out = g_att1 + (size_t)mt * 128 * NA;
#pragma unroll
        for (int mp = 0; mp < 4; mp++)
#pragma unroll
            for (int nn = 0; nn < 2; nn++) {
                float2 v = unpack2(acc[mp * 2 + nn]);
                int r = m8 + 2 * mp, c = c0 + n2 + nn;
                out[(size_t)r * NA + c] = v.x + be[c];
                out[(size_t)(r + 1) * NA + c] = v.y + be[c];
            }
    } else {
        int b2 = bx - 5000;
        const float* W = (b2 < 16) ? Wh0 : Wc0;
        const float* bias = (b2 < 16) ? bh0 : bc0;
        float* out = (b2 < 16) ? g_h : g_c;
        int c0 = (b2 & 15) * 32;
        gemm128x32(g_mean, NENC, W, NH, c0, NENC, acc, As, Bs);
#pragma unroll
        for (int mp = 0; mp < 4; mp++)
#pragma unroll
            for (int nn = 0; nn < 2; nn++) {
                float2 v = unpack2(acc[mp * 2 + nn]);
                int r = m8 + 2 * mp, c = c0 + n2 + nn;
                out[r * NH + c] = v.x + bias[c];
                out[(r + 1) * NH + c] = v.y + bias[c];
            }
    }
}

// ---------------- pre-loop: att2 + Wb partials from h0 (96 blocks) ----------------
__global__ __launch_bounds__(256, 2) void k_gemms0(const float* __restrict__ Wd,
                                                   const float* __restrict__ Wb) {
    __shared__ __align__(16) float As[KC * 128];
    __shared__ __align__(16) float2 Bs[KC * 32];
    int bx = blockIdx.x;
    unsigned long long acc[8];
    if (bx < 32) {
        int ks = bx & 3, tile = bx >> 2;
        gemm128x32(g_h + ks * 128, NH, Wd + (size_t)(ks * 128) * NA, NA, tile * 32, 128, acc, As,
                   Bs);
        store_tile_raw(g_a2p[ks], NA, tile * 32, acc);
    } else {
        int idx = bx - 32;
        int ks = idx & 3, tile = idx >> 2;
        gemm128x32(g_h + ks * 128, NH, Wb + (size_t)(ks * 128) * NENC, NENC, tile * 32, 128, acc,
                   As, Bs);
        store_tile_raw(g_gtp[ks], NENC, tile * 32, acc);
    }
}

// ---------------- K1: FUSED e-pass + distributed softmax + awe + comb (chunk 0) ----------------
// 512 blocks = 128 b x 4 p-chunks; co-resident via launch_bounds(256,4) (<=64 regs).
__global__ __launch_bounds__(256, 4) void k_att(const float* __restrict__ enc,
                                                const float* __restrict__ wf,
                                                const float* __restrict__ bd,
                                                const float* __restrict__ bb, int t) {
    __shared__ __align__(16) float att2s[NA];
    __shared__ __align__(16) float wfs[NA];
    __shared__ float es[CHK + 3];
    __shared__ float red[256];
    __shared__ __align__(16) float4 part[128];
    int bx = blockIdx.x, tid = threadIdx.x;
    int b = bx >> 2, chunk = bx & 3;
    int pstart = chunk * CHK;
    int len = (chunk < 3) ? CHK : (NP - 3 * CHK);
    att2s[tid] = g_a2p[0][b * NA + tid] + g_a2p[1][b * NA + tid] + g_a2p[2][b * NA + tid] +
                 g_a2p[3][b * NA + tid] + bd[tid];
    wfs[tid] = wf[tid];
    __syncthreads();
    // ---- phase 1: energies for this chunk -> smem ----
    {
        int wid = tid >> 5, lane = tid & 31;
        int sub = lane & 15, pofs = lane >> 4;  // 16 lanes per p
        const float* base = g_att1 + (size_t)b * NP * NA;
        float4 a[4], w[4];
#pragma unroll
        for (int j = 0; j < 4; j++) {
            a[j] = ((const float4*)att2s)[sub * 4 + j];
            w[j] = ((const float4*)wfs)[sub * 4 + j];
        }
#pragma unroll
        for (int it = 0; it < 10; it++) {
            int rel = it * 16 + wid * 2 + pofs;
            int p = pstart + (rel < len ? rel : 0);
            const float4* ptr = (const float4*)(base + (size_t)p * NA) + sub * 4;
            float4 v0 = ptr[0], v1 = ptr[1], v2 = ptr[2], v3 = ptr[3];
            float s = fmaxf(v0.x + a[0].x, 0.f) * w[0].x + fmaxf(v0.y + a[0].y, 0.f) * w[0].y +
                      fmaxf(v0.z + a[0].z, 0.f) * w[0].z + fmaxf(v0.w + a[0].w, 0.f) * w[0].w;
            s += fmaxf(v1.x + a[1].x, 0.f) * w[1].x + fmaxf(v1.y + a[1].y, 0.f) * w[1].y +
                 fmaxf(v1.z + a[1].z, 0.f) * w[1].z + fmaxf(v1.w + a[1].w, 0.f) * w[1].w;
            s += fmaxf(v2.x + a[2].x, 0.f) * w[2].x + fmaxf(v2.y + a[2].y, 0.f) * w[2].y +
                 fmaxf(v2.z + a[2].z, 0.f) * w[2].z + fmaxf(v2.w + a[2].w, 0.f) * w[2].w;
            s += fmaxf(v3.x + a[3].x, 0.f) * w[3].x + fmaxf(v3.y + a[3].y, 0.f) * w[3].y +
                 fmaxf(v3.z + a[3].z, 0.f) * w[3].z + fmaxf(v3.w + a[3].w, 0.f) * w[3].w;
            s += __shfl_xor_sync(0xffffffffu, s, 1);
            s += __shfl_xor_sync(0xffffffffu, s, 2);
            s += __shfl_xor_sync(0xffffffffu, s, 4);
            s += __shfl_xor_sync(0xffffffffu, s, 8);
            if (rel < len && sub == 0) es[rel] = s;
        }
    }
    __syncthreads();
    // ---- phase 2: local stats, publish, handshake ----
    float ev = (tid < len) ? es[tid] : -INFINITY;
    red[tid] = ev;
    __syncthreads();
    for (int s2 = 128; s2 > 0; s2 >>= 1) {
        if (tid < s2) red[tid] = fmaxf(red[tid], red[tid + s2]);
        __syncthreads();
    }
    float Mc = red[0];
    __syncthreads();
    red[tid] = (tid < len) ? expf(ev - Mc) : 0.f;
    __syncthreads();
    for (int s2 = 128; s2 > 0; s2 >>= 1) {
        if (tid < s2) red[tid] += red[tid + s2];
        __syncthreads();
    }
    float Sc = red[0];
    if (tid == 0) {
        g_stat[b * 8 + chunk * 2 + 0] = Mc;
        g_stat[b * 8 + chunk * 2 + 1] = Sc;
        __threadfence();
        atomicAdd(&g_cnt[b], 1);
        int target = 4 * (t + 1);
        while (((volatile int*)g_cnt)[b] < target) __nanosleep(64);
    }
    __syncthreads();
    __threadfence();
    float m0 = __ldcg(&g_stat[b * 8 + 0]), s0 = __ldcg(&g_stat[b * 8 + 1]);
    float m1 = __ldcg(&g_stat[b * 8 + 2]), s1 = __ldcg(&g_stat[b * 8 + 3]);
    float m2 = __ldcg(&g_stat[b * 8 + 4]), s2v = __ldcg(&g_stat[b * 8 + 5]);
    float m3 = __ldcg(&g_stat[b * 8 + 6]), s3 = __ldcg(&g_stat[b * 8 + 7]);
    float M = fmaxf(fmaxf(m0, m1), fmaxf(m2, m3));
    float S = ((s0 * expf(m0 - M) + s1 * expf(m1 - M)) + s2v * expf(m2 - M)) + s3 * expf(m3 - M);
    float inv = 1.f / S;
    if (tid < len) es[tid] = expf(ev - M) * inv;
    __syncthreads();
    // ---- phase 3: awe partial for this chunk ----
    int cq = tid & 127, pg = tid >> 7;
    const float4* eb = (const float4*)(enc + (size_t)b * NP * NENC + (size_t)pstart * NENC) + cq;
    float4 acc = make_float4(0.f, 0.f, 0.f, 0.f);
#pragma unroll 8
    for (int p = pg; p < len; p += 2) {
        float al = es[p];
        float4 v = eb[(size_t)p * 128];
        acc.x += al * v.x;
        acc.y += al * v.y;
        acc.z += al * v.z;
        acc.w += al * v.w;
    }
    if (pg == 1) part[cq] = acc;
    __syncthreads();
    if (pg == 0) {
        float4 pv = part[cq];
        acc.x += pv.x;
        acc.y += pv.y;
        acc.z += pv.z;
        acc.w += pv.w;
        ((float4*)(g_xp[chunk] + b * NENC))[cq] = acc;
    }
    __threadfence();
    __syncthreads();
    if (tid == 0) atomicAdd(&g_cnt2[b], 1);
    // ---- phase 4 (chunk 0 only): combine awe partials + gate -> g_x ----
    if (chunk == 0) {
        if (tid == 0) {
            int tgt = 4 * (t + 1);
            while (((volatile int*)g_cnt2)[b] < tgt) __nanosleep(32);
        }
        __syncthreads();
        __threadfence();
        for (int c = tid; c < NENC; c += 256) {
            float aw = ((__ldcg(&g_xp[0][b * NENC + c]) + __ldcg(&g_xp[1][b * NENC + c])) +
                        __ldcg(&g_xp[2][b * NENC + c])) +
                       __ldcg(&g_xp[3][b * NENC + c]);
            float gt = sigmoidf_(g_gtp[0][b * NENC + c] + g_gtp[1][b * NENC + c] +
                                 g_gtp[2][b * NENC + c] + g_gtp[3][b * NENC + c] + bb[c]);
            g_x[b * NENC + c] = aw * gt;
        }
    }
}

// ---------------- K2: Whh (128) + Wih (128) GEMMs + done-flag (block 0) ----------------
__global__ __launch_bounds__(256, 2) void k_whw(const float* __restrict__ Whh,
                                                const float* __restrict__ Wih) {
    __shared__ __align__(16) float As[KC * 128];
    __shared__ __align__(16) float2 Bs[KC * 32];
    int bx = blockIdx.x, tid = threadIdx.x;
    if (bx == 0) {  // done flag from previous step's row argmaxes
        float* dv = As;
        int* dfi = (int*)(As + 192);
        if (tid < 128) {
            dv[tid] = g_rowval[tid];
            dfi[tid] = g_rowflat[tid];
        }
        __syncthreads();
        for (int s = 64; s > 0; s >>= 1) {
            if (tid < s) {
                float ov = dv[tid + s];
                int of = dfi[tid + s];
                if (ov > dv[tid] || (ov == dv[tid] && of < dfi[tid])) {
                    dv[tid] = ov;
                    dfi[tid] = of;
                }
            }
            __syncthreads();
        }
        if (tid == 0 && dfi[0] == END_TOK) g_done[0] = 1;
        __syncthreads();
    }
    unsigned long long acc[8];
    if (bx < 128) {  // Whh: 64 col-tiles x 2 K-splits
        int ks = bx & 1, tile = bx >> 1;
        gemm128x32(g_h + ks * 256, NH, Whh + (size_t)(ks * 256) * NG, NG, tile * 32, 256, acc, As,
                   Bs);
        store_tile_raw(g_gw[ks], NG, tile * 32, acc);
    } else {  // awe @ Wih[256:768]: 64 col-tiles x 2 K-splits
        int idx = bx - 128;
        int ks = idx & 1, tile = idx >> 1;
        gemm128x32(g_x + ks * 256, NH, Wih + (size_t)(NE + ks * 256) * NG, NG, tile * 32, 256,
                   acc, As, Bs);
        store_tile_raw(g_wp[ks], NG, tile * 32, acc);
    }
}

// ---------------- K3: FUSED step (blocks 0-127) + next-step att2/Wb GEMMs (128-223) ----------------
// 224 blocks, launch_bounds(256,2) -> 2/SM x 148 = 296 slots >= 224: co-resident, spin is safe.
__global__ __launch_bounds__(256, 2) void k_sg(const float* __restrict__ bfc,
                                               const float* __restrict__ Wd,
                                               const float* __restrict__ Wb,
                                               float* __restrict__ out, int t) {
    __shared__ __align__(16) union {
        struct {
            float As[KC * 128];
            float2 Bs[KC * 32];
        } g;
        struct {
            float hs[NH];
            float pv[128];
            int pi_[128];
        } s;
    } sm;
    int bx = blockIdx.x, tid = threadIdx.x;
    if (bx < NB) {
        // ================= step block: batch row b =================
        int b = bx, wid = tid >> 5, lane = tid & 31;
        int tok = g_tok[b];
        const float* ew = g_embW + tok * NG;
#pragma unroll
        for (int half = 0; half < 2; half++) {
            int jh = tid + half * 256;
            float gv4[4];
#pragma unroll
            for (int gi = 0; gi < 4; gi++) {
                int jj = jh + gi * 512;
                float v = (g_gw[0][b * NG + jj] + g_gw[1][b * NG + jj]) +
                          (g_wp[0][b * NG + jj] + g_wp[1][b * NG + jj]);
                v += ew[jj] + g_lstmb[jj];
                gv4[gi] = v;
            }
            float c = g_c[b * NH + jh];
            float cn = sigmoidf_(gv4[1]) * c + sigmoidf_(gv4[0]) * tanhf(gv4[2]);
            float hn = sigmoidf_(gv4[3]) * tanhf(cn);
            g_c[b * NH + jh] = cn;
            g_h[b * NH + jh] = hn;
            sm.s.hs[jh] = hn;
        }
        // publish h for the next-step GEMM blocks
        __threadfence();
        __syncthreads();
        if (tid == 0) atomicAdd(&g_cnt3, 1);
        if (tid < 128) {
            sm.s.pv[tid] = -INFINITY;
            sm.s.pi_[tid] = tid;
        }
        __syncthreads();
        int done = g_done[0];
        const float4* hs4 = (const float4*)sm.s.hs;
        for (int col = wid; col < NV; col += 8) {
            const float4* wr = (const float4*)(g_WfcT + col * NH);
            float s = 0.f;
#pragma unroll
            for (int i = 0; i < 4; i++) {
                float4 h4 = hs4[lane + 32 * i];
                float4 w4 = wr[lane + 32 * i];
                s += h4.x * w4.x + h4.y * w4.y + h4.z * w4.z + h4.w * w4.w;
            }
#pragma unroll
            for (int o = 16; o > 0; o >>= 1) s += __shfl_down_sync(0xffffffffu, s, o);
            if (lane == 0) {
                s += bfc[col];
                out[(size_t)b * NT * NV + (size_t)t * NV + col] = done ? 0.f : s;
                sm.s.pv[col] = s;
                sm.s.pi_[col] = col;
            }
        }
        __syncthreads();
        for (int s2 = 64; s2 > 0; s2 >>= 1) {
            if (tid < s2) {
                float ov = sm.s.pv[tid + s2];
                int oi = sm.s.pi_[tid + s2];
                if (ov > sm.s.pv[tid] || (ov == sm.s.pv[tid] && oi < sm.s.pi_[tid])) {
                    sm.s.pv[tid] = ov;
                    sm.s.pi_[tid] = oi;
                }
            }
            __syncthreads();
        }
        if (tid == 0) {
            g_rowval[b] = sm.s.pv[0];
            g_rowflat[b] = b * NV + sm.s.pi_[0];
            g_tok[b] = sm.s.pi_[0];
        }
        return;
    }
    // ================= next-step GEMM block =================
    if (tid == 0) {
        int target = NB * (t + 1);
        while (((volatile int*)&g_cnt3)[0] < target) __nanosleep(64);
    }
    __syncthreads();
    __threadfence();
    int idx = bx - NB;
    unsigned long long acc[8];
    if (idx < 32) {  // att2 partials: 8 tiles x 4 K-splits
        int ks = idx & 3, tile = idx >> 2;
        gemm128x32(g_h + ks * 128, NH, Wd + (size_t)(ks * 128) * NA, NA, tile * 32, 128, acc,
                   sm.g.As, sm.g.Bs);
        store_tile_raw(g_a2p[ks], NA, tile * 32, acc);
    } else {  // Wb gate partials: 16 tiles x 4 K-splits
        int i2 = idx - 32;
        int ks = i2 & 3, tile = i2 >> 2;
        gemm128x32(g_h + ks * 128, NH, Wb + (size_t)(ks * 128) * NENC, NENC, tile * 32, 128, acc,
                   sm.g.As, sm.g.Bs);
        store_tile_raw(g_gtp[ks], NENC, tile * 32, acc);
    }
}

extern "C" void kernel_launch(void* const* d_in, const int* in_sizes, int n_in,
                              void* d_out, int out_size) {
    (void)in_sizes; (void)n_in; (void)out_size;
    const float* enc = (const float*)d_in[0];
    const float* emb = (const float*)d_in[1];
    const float* We  = (const float*)d_in[2];
    const float* be  = (const float*)d_in[3];
    const float* Wd  = (const float*)d_in[4];
    const float* bd  = (const float*)d_in[5];
    const float* wf  = (const float*)d_in[6];
    const float* Wh0 = (const float*)d_in[8];
    const float* bh0 = (const float*)d_in[9];
    const float* Wc0 = (const float*)d_in[10];
    const float* bc0 = (const float*)d_in[11];
    const float* Wb  = (const float*)d_in[12];
    const float* bb  = (const float*)d_in[13];
    const float* Wih = (const float*)d_in[14];
    const float* Whh = (const float*)d_in[15];
    const float* bih = (const float*)d_in[16];
    const float* bhh = (const float*)d_in[17];
    const float* Wfc = (const float*)d_in[18];
    const float* bfc = (const float*)d_in[19];
    float* out = (float*)d_out;

    k_init<<<NB + NV + 4 + NV * 4, 512>>>(enc, Wfc, bih, bhh, emb, Wih);
    k_att1<<<5032, 256>>>(enc, We, be, Wh0, bh0, Wc0, bc0);
    k_gemms0<<<96, 256>>>(Wd, Wb);
    for (int t = 0; t < NT; t++) {
        k_att<<<512, 256>>>(enc, wf, bd, bb, t);
        k_whw<<<256, 256>>>(Whh, Wih);
        k_sg<<<224, 256>>>(bfc, Wd, Wb, out, t);
    }
}

// round 16
// speedup vs baseline: 1.0176x; 1.0176x over previous
#include <cuda_runtime.h>
#include <math.h>

#define NB 128
#define NP 625
#define NENC 512
#define NA 256
#define NE 256
#define NH 512
#define NV 70
#define NT 70
#define NG 2048
#define KC 64
#define START_TOK 68
#define END_TOK 69
#define CHK 157  // p-chunk length (last chunk = 154)

// ---------------- scratch ----------------
__device__ float g_att1[NB * NP * NA];   // 81.92MB
__device__ float g_h[NB * NH];
__device__ float g_c[NB * NH];
__device__ float g_mean[NB * NENC];
__device__ float g_x[NB * NH];           // gated awe
__device__ float g_a2p[4][NB * NA];      // att2 K-partials
__device__ float g_gtp[4][NB * NENC];    // gate  K-partials
__device__ float g_xp[4][NB * NENC];     // awe chunk-partials (pre-scaled)
__device__ float g_gw[2][NB * NG];       // h@Whh K-partials
__device__ float g_wp[2][NB * NG];       // awe@Wih2 K-partials
__device__ float g_embW[NV * NG];        // emb @ Wih[0:256] per vocab token
__device__ float g_lstmb[NG];            // bih + bhh
__device__ float g_WfcT[NV * NH];
__device__ float g_stat[NB * 8];         // per-b, per-chunk (M, S)
__device__ float g_rowval[NB];
__device__ int   g_rowflat[NB];
__device__ int   g_tok[NB];
__device__ int   g_cnt[NB];              // softmax-stats epoch counter (4/step/b)
__device__ int   g_cnt2[NB];             // awe-partials epoch counter (4/step/b)
__device__ int   g_done[1];

// ---------------- f32x2 helpers ----------------
__device__ __forceinline__ unsigned long long fma2(unsigned long long a, unsigned long long b,
                                                   unsigned long long c) {
    unsigned long long d;
    asm("fma.rn.f32x2 %0, %1, %2, %3;" : "=l"(d) : "l"(a), "l"(b), "l"(c));
    return d;
}
__device__ __forceinline__ float2 unpack2(unsigned long long v) {
    float2 r;
    asm("mov.b64 {%0, %1}, %2;" : "=f"(r.x), "=f"(r.y) : "l"(v));
    return r;
}
__device__ __forceinline__ float sigmoidf_(float x) { return 1.f / (1.f + expf(-x)); }

// ---------------- core GEMM tile: C[128, c0:c0+32] = A[128,K] @ W[K, ldw] ----------------
__device__ __forceinline__ void gemm128x32(const float* __restrict__ A, int lda,
                                           const float* __restrict__ W, int ldw, int c0, int K,
                                           unsigned long long acc[8], float* As, float2* Bs) {
    const int tid = threadIdx.x;
    const int ai = (tid >> 4) * 2;
    const int bi = tid & 15;
    const int la_m = tid & 127, la_k = (tid >> 7) * 32;
    const int lb_n = tid & 31, lb_k = tid >> 5;
#pragma unroll
    for (int j = 0; j < 8; j++) acc[j] = 0ULL;
    float4 pa[8];
    float pb[8];
    const float* Arow = A + (size_t)la_m * lda + la_k;
    const float* Wcol = W + (size_t)lb_k * ldw + c0 + lb_n;
#pragma unroll
    for (int j = 0; j < 8; j++) pa[j] = *(const float4*)(Arow + 4 * j);
#pragma unroll
    for (int j = 0; j < 8; j++) pb[j] = Wcol[(size_t)(8 * j) * ldw];
    const int nc = K / KC;
    for (int ch = 0;;) {
#pragma unroll
        for (int j = 0; j < 8; j++) {
            float4 v = pa[j];
            int kk = la_k + 4 * j;
            As[(kk + 0) * 128 + la_m] = v.x;
            As[(kk + 1) * 128 + la_m] = v.y;
            As[(kk + 2) * 128 + la_m] = v.z;
            As[(kk + 3) * 128 + la_m] = v.w;
        }
#pragma unroll
        for (int j = 0; j < 8; j++) Bs[(lb_k + 8 * j) * 32 + lb_n] = make_float2(pb[j], pb[j]);
        __syncthreads();
        if (ch + 1 < nc) {
            const float* Ar2 = Arow + (ch + 1) * KC;
            const float* Wc2 = Wcol + (size_t)((ch + 1) * KC) * ldw;
#pragma unroll
            for (int j = 0; j < 8; j++) pa[j] = *(const float4*)(Ar2 + 4 * j);
#pragma unroll
            for (int j = 0; j < 8; j++) pb[j] = Wc2[(size_t)(8 * j) * ldw];
        }
        const ulonglong2* As2 = (const ulonglong2*)As;
        const ulonglong2* Bs2 = (const ulonglong2*)Bs;
#pragma unroll 8
        for (int k = 0; k < KC; k++) {
            ulonglong2 bv = Bs2[k * 16 + bi];
            ulonglong2 a01 = As2[k * 32 + ai];
            ulonglong2 a23 = As2[k * 32 + ai + 1];
            acc[0] = fma2(a01.x, bv.x, acc[0]);
            acc[1] = fma2(a01.x, bv.y, acc[1]);
            acc[2] = fma2(a01.y, bv.x, acc[2]);
            acc[3] = fma2(a01.y, bv.y, acc[3]);
            acc[4] = fma2(a23.x, bv.x, acc[4]);
            acc[5] = fma2(a23.x, bv.y, acc[5]);
            acc[6] = fma2(a23.y, bv.x, acc[6]);
            acc[7] = fma2(a23.y, bv.y, acc[7]);
        }
        __syncthreads();
        if (++ch == nc) break;
    }
}

__device__ __forceinline__ void store_tile_raw(float* out, int ldo, int c0,
                                               const unsigned long long acc[8]) {
    int tid = threadIdx.x;
    int m8 = (tid >> 4) * 8, n2 = (tid & 15) * 2;
#pragma unroll
    for (int mp = 0; mp < 4; mp++)
#pragma unroll
        for (int nn = 0; nn < 2; nn++) {
            float2 v = unpack2(acc[mp * 2 + nn]);
            int r = m8 + 2 * mp, c = c0 + n2 + nn;
            out[(size_t)r * ldo + c] = v.x;
            out[(size_t)(r + 1) * ldo + c] = v.y;
        }
}

// ---------------- init ----------------
__global__ void k_init(const float* __restrict__ enc, const float* __restrict__ Wfc,
                       const float* __restrict__ bih, const float* __restrict__ bhh,
                       const float* __restrict__ emb, const float* __restrict__ Wih) {
    __shared__ float es[NE];
    int bx = blockIdx.x, tid = threadIdx.x;  // 512 threads
    if (bx < NB) {
        const float* eb = enc + (size_t)bx * NP * NENC + tid;
        float s0 = 0.f, s1 = 0.f, s2 = 0.f, s3 = 0.f, s4 = 0.f;
#pragma unroll 5
        for (int p = 0; p < NP; p += 5) {
            s0 += eb[(size_t)(p + 0) * NENC];
            s1 += eb[(size_t)(p + 1) * NENC];
            s2 += eb[(size_t)(p + 2) * NENC];
            s3 += eb[(size_t)(p + 3) * NENC];
            s4 += eb[(size_t)(p + 4) * NENC];
        }
        g_mean[bx * NENC + tid] = (((s0 + s1) + (s2 + s3)) + s4) / 625.0f;
        if (tid == 0) {
            g_rowval[bx] = -INFINITY;
            g_rowflat[bx] = 0;
            g_tok[bx] = START_TOK;
            g_cnt[bx] = 0;
            g_cnt2[bx] = 0;
        }
        if (bx == 0 && tid == 0) g_done[0] = 0;
    } else if (bx < NB + NV) {
        int col = bx - NB;
        g_WfcT[col * NH + tid] = Wfc[tid * NV + col];
    } else if (bx < NB + NV + 4) {
        int j = (bx - NB - NV) * 512 + tid;
        g_lstmb[j] = bih[j] + bhh[j];
    } else {
        int idx = bx - (NB + NV + 4);
        int t = idx >> 2, seg = idx & 3;
        if (tid < NE) es[tid] = emb[t * NE + tid];
        __syncthreads();
        int col = seg * 512 + tid;
        float acc = 0.f;
#pragma unroll 8
        for (int k = 0; k < NE; k++) acc = fmaf(es[k], Wih[(size_t)k * NG + col], acc);
        g_embW[t * NG + col] = acc;
    }
}

// ---------------- att1 = enc @ We + be  +  h0/c0 (merged) ----------------
__global__ __launch_bounds__(256) void k_att1(const float* __restrict__ enc,
                                              const float* __restrict__ We,
                                              const float* __restrict__ be,
                                              const float* __restrict__ Wh0,
                                              const float* __restrict__ bh0,
                                              const float* __restrict__ Wc0,
                                              const float* __restrict__ bc0) {
    __shared__ __align__(16) float As[KC * 128];
    __shared__ __align__(16) float2 Bs[KC * 32];
    int bx = blockIdx.x, tid = threadIdx.x;
    unsigned long long acc[8];
    int m8 = (tid >> 4) * 8, n2 = (tid & 15) * 2;
    if (bx < 5000) {
        int mt = bx >> 3, c0 = (bx & 7) * 32;
        gemm128x32(enc + (size_t)mt * 128 * NENC, NENC, We, NA, c0, NENC, acc, As, Bs);
        float* out = g_att1 + (size_t)mt * 128 * NA;
#pragma unroll
        for (int mp = 0; mp < 4; mp++)
#pragma unroll
            for (int nn = 0; nn < 2; nn++) {
                float2 v = unpack2(acc[mp * 2 + nn]);
                int r = m8 + 2 * mp, c = c0 + n2 + nn;
                out[(size_t)r * NA + c] = v.x + be[c];
                out[(size_t)(r + 1) * NA + c] = v.y + be[c];
            }
    } else {
        int b2 = bx - 5000;
        const float* W = (b2 < 16) ? Wh0 : Wc0;
        const float* bias = (b2 < 16) ? bh0 : bc0;
        float* out = (b2 < 16) ? g_h : g_c;
        int c0 = (b2 & 15) * 32;
        gemm128x32(g_mean, NENC, W, NH, c0, NENC, acc, As, Bs);
#pragma unroll
        for (int mp = 0; mp < 4; mp++)
#pragma unroll
            for (int nn = 0; nn < 2; nn++) {
                float2 v = unpack2(acc[mp * 2 + nn]);
                int r = m8 + 2 * mp, c = c0 + n2 + nn;
                out[r * NH + c] = v.x + bias[c];
                out[(r + 1) * NH + c] = v.y + bias[c];
            }
    }
}

// ---------------- K1: h-GEMMs (att2 x32, Whh x128, Wb x64 = 224 blocks) + done-flag ----------------
__global__ __launch_bounds__(256, 2) void k_gemms(const float* __restrict__ Wd,
                                                  const float* __restrict__ Whh,
                                                  const float* __restrict__ Wb) {
    __shared__ __align__(16) float As[KC * 128];
    __shared__ __align__(16) float2 Bs[KC * 32];
    int bx = blockIdx.x, tid = threadIdx.x;
    if (bx == 0) {  // done flag from previous step's row argmaxes
        float* dv = As;
        int* dfi = (int*)(As + 192);
        if (tid < 128) {
            dv[tid] = g_rowval[tid];
            dfi[tid] = g_rowflat[tid];
        }
        __syncthreads();
        for (int s = 64; s > 0; s >>= 1) {
            if (tid < s) {
                float ov = dv[tid + s];
                int of = dfi[tid + s];
                if (ov > dv[tid] || (ov == dv[tid] && of < dfi[tid])) {
                    dv[tid] = ov;
                    dfi[tid] = of;
                }
            }
            __syncthreads();
        }
        if (tid == 0 && dfi[0] == END_TOK) g_done[0] = 1;
        __syncthreads();
    }
    unsigned long long acc[8];
    if (bx < 32) {  // att2 partials: 8 tiles x 4 K-splits
        int ks = bx & 3, tile = bx >> 2;
        gemm128x32(g_h + ks * 128, NH, Wd + (size_t)(ks * 128) * NA, NA, tile * 32, 128, acc, As,
                   Bs);
        store_tile_raw(g_a2p[ks], NA, tile * 32, acc);
    } else if (bx < 160) {  // Whh: 64 col-tiles x 2 K-splits
        int idx = bx - 32;
        int ks = idx & 1, tile = idx >> 1;
        gemm128x32(g_h + ks * 256, NH, Whh + (size_t)(ks * 256) * NG, NG, tile * 32, 256, acc, As,
                   Bs);
        store_tile_raw(g_gw[ks], NG, tile * 32, acc);
    } else {  // Wb gate partials: 16 tiles x 4 K-splits
        int idx = bx - 160;
        int ks = idx & 3, tile = idx >> 2;
        gemm128x32(g_h + ks * 128, NH, Wb + (size_t)(ks * 128) * NENC, NENC, tile * 32, 128, acc,
                   As, Bs);
        store_tile_raw(g_gtp[ks], NENC, tile * 32, acc);
    }
}

// ---------------- K2: FUSED e-pass + awe (local weights) + deferred softmax scale + comb ----------------
// 512 blocks = 128 b x 4 p-chunks; co-resident via launch_bounds(256,4). The softmax stats
// handshake happens AFTER both DRAM scans: chunk partial = exp(Mc-M)/S * sum_p exp(e_p-Mc)*enc_p.
__global__ __launch_bounds__(256, 4) void k_att(const float* __restrict__ enc,
                                                const float* __restrict__ wf,
                                                const float* __restrict__ bd,
                                                const float* __restrict__ bb, int t) {
    __shared__ __align__(16) float att2s[NA];
    __shared__ __align__(16) float wfs[NA];
    __shared__ float es[CHK + 3];
    __shared__ float red[256];
    __shared__ __align__(16) float4 part[128];
    int bx = blockIdx.x, tid = threadIdx.x;
    int b = bx >> 2, chunk = bx & 3;
    int pstart = chunk * CHK;
    int len = (chunk < 3) ? CHK : (NP - 3 * CHK);
    att2s[tid] = g_a2p[0][b * NA + tid] + g_a2p[1][b * NA + tid] + g_a2p[2][b * NA + tid] +
                 g_a2p[3][b * NA + tid] + bd[tid];
    wfs[tid] = wf[tid];
    __syncthreads();
    // ---- phase 1: energies for this chunk -> smem ----
    {
        int wid = tid >> 5, lane = tid & 31;
        int sub = lane & 15, pofs = lane >> 4;  // 16 lanes per p
        const float* base = g_att1 + (size_t)b * NP * NA;
        float4 a[4], w[4];
#pragma unroll
        for (int j = 0; j < 4; j++) {
            a[j] = ((const float4*)att2s)[sub * 4 + j];
            w[j] = ((const float4*)wfs)[sub * 4 + j];
        }
#pragma unroll
        for (int it = 0; it < 10; it++) {
            int rel = it * 16 + wid * 2 + pofs;
            int p = pstart + (rel < len ? rel : 0);
            const float4* ptr = (const float4*)(base + (size_t)p * NA) + sub * 4;
            float4 v0 = ptr[0], v1 = ptr[1], v2 = ptr[2], v3 = ptr[3];
            float s = fmaxf(v0.x + a[0].x, 0.f) * w[0].x + fmaxf(v0.y + a[0].y, 0.f) * w[0].y +
                      fmaxf(v0.z + a[0].z, 0.f) * w[0].z + fmaxf(v0.w + a[0].w, 0.f) * w[0].w;
            s += fmaxf(v1.x + a[1].x, 0.f) * w[1].x + fmaxf(v1.y + a[1].y, 0.f) * w[1].y +
                 fmaxf(v1.z + a[1].z, 0.f) * w[1].z + fmaxf(v1.w + a[1].w, 0.f) * w[1].w;
            s += fmaxf(v2.x + a[2].x, 0.f) * w[2].x + fmaxf(v2.y + a[2].y, 0.f) * w[2].y +
                 fmaxf(v2.z + a[2].z, 0.f) * w[2].z + fmaxf(v2.w + a[2].w, 0.f) * w[2].w;
            s += fmaxf(v3.x + a[3].x, 0.f) * w[3].x + fmaxf(v3.y + a[3].y, 0.f) * w[3].y +
                 fmaxf(v3.z + a[3].z, 0.f) * w[3].z + fmaxf(v3.w + a[3].w, 0.f) * w[3].w;
            s += __shfl_xor_sync(0xffffffffu, s, 1);
            s += __shfl_xor_sync(0xffffffffu, s, 2);
            s += __shfl_xor_sync(0xffffffffu, s, 4);
            s += __shfl_xor_sync(0xffffffffu, s, 8);
            if (rel < len && sub == 0) es[rel] = s;
        }
    }
    __syncthreads();
    // ---- phase 2: local stats (Mc, Sc), publish (NO wait), local weights in smem ----
    float ev = (tid < len) ? es[tid] : -INFINITY;
    red[tid] = ev;
    __syncthreads();
    for (int s2 = 128; s2 > 0; s2 >>= 1) {
        if (tid < s2) red[tid] = fmaxf(red[tid], red[tid + s2]);
        __syncthreads();
    }
    float Mc = red[0];
    __syncthreads();
    float ew_ = (tid < len) ? expf(ev - Mc) : 0.f;
    red[tid] = ew_;
    if (tid < len) es[tid] = ew_;  // local (unnormalized) weight
    __syncthreads();
    for (int s2 = 128; s2 > 0; s2 >>= 1) {
        if (tid < s2) red[tid] += red[tid + s2];
        __syncthreads();
    }
    float Sc = red[0];
    if (tid == 0) {
        g_stat[b * 8 + chunk * 2 + 0] = Mc;
        g_stat[b * 8 + chunk * 2 + 1] = Sc;
        __threadfence();
        atomicAdd(&g_cnt[b], 1);
    }
    __syncthreads();
    // ---- phase 3: awe partial with LOCAL weights (no cross-chunk dependency) ----
    int cq = tid & 127, pg = tid >> 7;
    const float4* eb = (const float4*)(enc + (size_t)b * NP * NENC + (size_t)pstart * NENC) + cq;
    float4 acc = make_float4(0.f, 0.f, 0.f, 0.f);
#pragma unroll 8
    for (int p = pg; p < len; p += 2) {
        float al = es[p];
        float4 v = eb[(size_t)p * 128];
        acc.x += al * v.x;
        acc.y += al * v.y;
        acc.z += al * v.z;
        acc.w += al * v.w;
    }
    if (pg == 1) part[cq] = acc;
    __syncthreads();
    // ---- phase 4: NOW wait for all chunks' stats (overlaps chunk skew), scale, write ----
    if (tid == 0) {
        int target = 4 * (t + 1);
        while (((volatile int*)g_cnt)[b] < target) __nanosleep(64);
    }
    __syncthreads();
    __threadfence();
    float m0 = __ldcg(&g_stat[b * 8 + 0]), s0 = __ldcg(&g_stat[b * 8 + 1]);
    float m1 = __ldcg(&g_stat[b * 8 + 2]), s1 = __ldcg(&g_stat[b * 8 + 3]);
    float m2 = __ldcg(&g_stat[b * 8 + 4]), s2v = __ldcg(&g_stat[b * 8 + 5]);
    float m3 = __ldcg(&g_stat[b * 8 + 6]), s3 = __ldcg(&g_stat[b * 8 + 7]);
    float M = fmaxf(fmaxf(m0, m1), fmaxf(m2, m3));
    float S = ((s0 * expf(m0 - M) + s1 * expf(m1 - M)) + s2v * expf(m2 - M)) + s3 * expf(m3 - M);
    float scale = expf(Mc - M) / S;
    if (pg == 0) {
        float4 pv = part[cq];
        acc.x = (acc.x + pv.x) * scale;
        acc.y = (acc.y + pv.y) * scale;
        acc.z = (acc.z + pv.z) * scale;
        acc.w = (acc.w + pv.w) * scale;
        ((float4*)(g_xp[chunk] + b * NENC))[cq] = acc;
    }
    __threadfence();
    __syncthreads();
    if (tid == 0) atomicAdd(&g_cnt2[b], 1);
    // ---- phase 5 (chunk 0 only): combine scaled partials + gate -> g_x ----
    if (chunk == 0) {
        if (tid == 0) {
            int tgt = 4 * (t + 1);
            while (((volatile int*)g_cnt2)[b] < tgt) __nanosleep(32);
        }
        __syncthreads();
        __threadfence();
        for (int c = tid; c < NENC; c += 256) {
            float aw = ((__ldcg(&g_xp[0][b * NENC + c]) + __ldcg(&g_xp[1][b * NENC + c])) +
                        __ldcg(&g_xp[2][b * NENC + c])) +
                       __ldcg(&g_xp[3][b * NENC + c]);
            float gt = sigmoidf_(g_gtp[0][b * NENC + c] + g_gtp[1][b * NENC + c] +
                                 g_gtp[2][b * NENC + c] + g_gtp[3][b * NENC + c] + bb[c]);
            g_x[b * NENC + c] = aw * gt;
        }
    }
}

// ---------------- K3: awe @ Wih[256:768]  (64 col-tiles x 2 K-splits = 128 blocks) ----------------
__global__ __launch_bounds__(256, 2) void k_wih(const float* __restrict__ Wih) {
    __shared__ __align__(16) float As[KC * 128];
    __shared__ __align__(16) float2 Bs[KC * 32];
    int bx = blockIdx.x;
    int ks = bx & 1, tile = bx >> 1;
    unsigned long long acc[8];
    gemm128x32(g_x + ks * 256, NH, Wih + (size_t)(NE + ks * 256) * NG, NG, tile * 32, 256, acc,
               As, Bs);
    store_tile_raw(g_wp[ks], NG, tile * 32, acc);
}

// ---------------- K4: gate-sum + LSTM + preds + argmax + token feedback ----------------
__global__ __launch_bounds__(512) void k_step(const float* __restrict__ bfc,
                                              float* __restrict__ out, int t) {
    int b = blockIdx.x, tid = threadIdx.x, wid = tid >> 5, lane = tid & 31;
    __shared__ __align__(16) float hs[NH];
    __shared__ float pv[128];
    __shared__ int pi_[128];
    int tok = g_tok[b];
    {
        int j = tid;
        const float* ew = g_embW + tok * NG;
        float gv4[4];
#pragma unroll
        for (int gi = 0; gi < 4; gi++) {
            int jj = j + gi * 512;
            float v = (g_gw[0][b * NG + jj] + g_gw[1][b * NG + jj]) +
                      (g_wp[0][b * NG + jj] + g_wp[1][b * NG + jj]);
            v += ew[jj] + g_lstmb[jj];
            gv4[gi] = v;
        }
        float c = g_c[b * NH + j];
        float cn = sigmoidf_(gv4[1]) * c + sigmoidf_(gv4[0]) * tanhf(gv4[2]);
        float hn = sigmoidf_(gv4[3]) * tanhf(cn);
        g_c[b * NH + j] = cn;
        g_h[b * NH + j] = hn;
        hs[j] = hn;
    }
    if (tid < 128) {
        pv[tid] = -INFINITY;
        pi_[tid] = tid;
    }
    __syncthreads();
    int done = g_done[0];
    const float4* hs4 = (const float4*)hs;
    for (int col = wid; col < NV; col += 16) {
        const float4* wr = (const float4*)(g_WfcT + col * NH);
        float s = 0.f;
#pragma unroll
        for (int i = 0; i < 4; i++) {
            float4 h4 = hs4[lane + 32 * i];
            float4 w4 = wr[lane + 32 * i];
            s += h4.x * w4.x + h4.y * w4.y + h4.z * w4.z + h4.w * w4.w;
        }
#pragma unroll
        for (int o = 16; o > 0; o >>= 1) s += __shfl_down_sync(0xffffffffu, s, o);
        if (lane == 0) {
            s += bfc[col];
            out[(size_t)b * NT * NV + (size_t)t * NV + col] = done ? 0.f : s;
            pv[col] = s;
            pi_[col] = col;
        }
    }
    __syncthreads();
    for (int s2 = 64; s2 > 0; s2 >>= 1) {
        if (tid < s2) {
            float ov = pv[tid + s2];
            int oi = pi_[tid + s2];
            if (ov > pv[tid] || (ov == pv[tid] && oi < pi_[tid])) {
                pv[tid] = ov;
                pi_[tid] = oi;
            }
        }
        __syncthreads();
    }
    if (tid == 0) {
        g_rowval[b] = pv[0];
        g_rowflat[b] = b * NV + pi_[0];
        g_tok[b] = pi_[0];
    }
}

extern "C" void kernel_launch(void* const* d_in, const int* in_sizes, int n_in,
                              void* d_out, int out_size) {
    (void)in_sizes; (void)n_in; (void)out_size;
    const float* enc = (const float*)d_in[0];
    const float* emb = (const float*)d_in[1];
    const float* We  = (const float*)d_in[2];
    const float* be  = (const float*)d_in[3];
    const float* Wd  = (const float*)d_in[4];
    const float* bd  = (const float*)d_in[5];
    const float* wf  = (const float*)d_in[6];
    const float* Wh0 = (const float*)d_in[8];
    const float* bh0 = (const float*)d_in[9];
    const float* Wc0 = (const float*)d_in[10];
    const float* bc0 = (const float*)d_in[11];
    const float* Wb  = (const float*)d_in[12];
    const float* bb  = (const float*)d_in[13];
    const float* Wih = (const float*)d_in[14];
    const float* Whh = (const float*)d_in[15];
    const float* bih = (const float*)d_in[16];
    const float* bhh = (const float*)d_in[17];
    const float* Wfc = (const float*)d_in[18];
    const float* bfc = (const float*)d_in[19];
    float* out = (float*)d_out;

    k_init<<<NB + NV + 4 + NV * 4, 512>>>(enc, Wfc, bih, bhh, emb, Wih);
    k_att1<<<5032, 256>>>(enc, We, be, Wh0, bh0, Wc0, bc0);
    for (int t = 0; t < NT; t++) {
        k_gemms<<<224, 256>>>(Wd, Whh, Wb);
        k_att<<<512, 256>>>(enc, wf, bd, bb, t);
        k_wih<<<128, 256>>>(Wih);
        k_step<<<NB, 512>>>(bfc, out, t);
    }
}